// round 16
// baseline (speedup 1.0000x reference)
#include <cuda_runtime.h>
#include <cuda_bf16.h>

// Problem constants
#define B_  16
#define R_  64
#define S_  128
#define M_  64
#define L_  128
#define E_  4032            // R*R - R

// Output layout (float elements), 5 concatenated outputs:
#define OFF_INC_ADD  0ull
#define OFF_INC_GAIN 131072ull
#define OFF_MEAN     262144ull
#define OFF_LOG      4456448ull
#define OFF_MSG      8650752ull

// Shared layout (floats), total 24768 floats = 99072 B dynamic smem  [= R14]
#define XS_OFF    0            // xs[b][s] stride 128: 2048
#define PA_OFF    2048         // SubA weights: w2 64*132=8448 / w3 128*68=8704
#define QB_OFF    10752        // SubB weights
#define SMEAN_OFF 19456        // smean[b][m] stride 68: 1088 -> ends 20544
#define SADD_OFF  20544        // sadd[b][l]  stride 132: 2112 -> ends 22656
#define SGAIN_OFF 22656        // sgain[b][l] stride 132: 2112 -> ends 24768
#define SMEM_FLOATS 24768
#define W2S 132                // phase-2 weight row stride (128+4)
#define W3S 68                 // phase-3 weight row stride (64+4)
#define SMS 68                 // smean row stride
#define SAS 132                // sadd/sgain row stride

typedef unsigned long long ull;

// ---------------- packed f32x2 helpers ----------------
__device__ __forceinline__ ull fma2(ull a, ull b, ull c) {
    ull d;
    asm("fma.rn.f32x2 %0, %1, %2, %3;" : "=l"(d) : "l"(a), "l"(b), "l"(c));
    return d;
}
__device__ __forceinline__ void unpk(ull v, float& lo, float& hi) {
    asm("mov.b64 {%0, %1}, %2;" : "=f"(lo), "=f"(hi) : "l"(v));
}
__device__ __forceinline__ void red_add_v4(float* p, float4 v) {
    asm volatile("red.global.add.v4.f32 [%0], {%1, %2, %3, %4};"
                 :: "l"(p), "f"(v.x), "f"(v.y), "f"(v.z), "f"(v.w) : "memory");
}
__device__ __forceinline__ void cpa16(float* dst_smem, const float* src) {
    unsigned sa = (unsigned)__cvta_generic_to_shared(dst_smem);
    asm volatile("cp.async.cg.shared.global [%0], [%1], 16;" :: "r"(sa), "l"(src));
}
__device__ __forceinline__ void cp_commit() { asm volatile("cp.async.commit_group;"); }
__device__ __forceinline__ void cp_wait0()  { asm volatile("cp.async.wait_group 0;" ::: "memory"); }
__device__ __forceinline__ void bar_sync(int id, int cnt) {
    asm volatile("bar.sync %0, %1;" :: "r"(id), "r"(cnt) : "memory");
}
__device__ __forceinline__ void bar_arrive(int id, int cnt) {
    asm volatile("bar.arrive %0, %1;" :: "r"(id), "r"(cnt) : "memory");
}

// ---------------- init: zero inc regions + scat diagonals (vectorized) ----
__global__ void init_kernel(float* __restrict__ out) {
    int idx = blockIdx.x * blockDim.x + threadIdx.x;   // grid covers 65536
    if (idx < 65536)
        reinterpret_cast<float4*>(out)[idx] = make_float4(0.f, 0.f, 0.f, 0.f);
    if (idx < 49152) {
        int o    = idx >> 14;              // 0..2
        int rest = idx & 16383;
        int b    = rest >> 10;             // 0..15
        int r    = (rest >> 4) & 63;       // 0..63
        int q    = rest & 15;              // 0..15
        ull base = (o == 0) ? OFF_MEAN : ((o == 1) ? OFF_LOG : OFF_MSG);
        ull a = base + (((ull)(b * R_ + r) * R_ + r) * M_) + q * 4;
        *reinterpret_cast<float4*>(out + a) = make_float4(0.f, 0.f, 0.f, 0.f);
    }
}

// ------- main: one block per edge, 512 threads, two 256-thread subs -------
__global__ __launch_bounds__(512, 2) void edge_kernel(
    const float* __restrict__ source,
    const float* __restrict__ mean_w,
    const float* __restrict__ mean_b,
    const float* __restrict__ logstd_w,
    const float* __restrict__ logstd_b,
    const float* __restrict__ add_w,
    const float* __restrict__ gain_w,
    float* __restrict__ out)
{
    extern __shared__ float sm[];
    float* xs    = sm + XS_OFF;      // [b][s] stride 128 (warp-broadcast reads)
    float* smean = sm + SMEAN_OFF;   // [b][m] stride 68
    float* sadd  = sm + SADD_OFF;    // [b][l] stride 132
    float* sgain = sm + SGAIN_OFF;

    const int e = blockIdx.x;
    const int s_idx = e / (R_ - 1);
    const int rem   = e % (R_ - 1);
    const int t_idx = rem + (rem >= s_idx ? 1 : 0);
    const int tid = threadIdx.x;
    const bool isA = (tid < 256);
    const int  u   = tid & 255;
    float* WB = sm + (isA ? PA_OFF : QB_OFF);

    // ---- staging 1: xs (one 16B chunk per thread) + phase-2 weights ----
    {
        int b = tid >> 5, c = tid & 31;        // 512 chunks exactly
        cpa16(xs + 4 * tid,
              source + (ull)b * (R_ * S_) + (ull)s_idx * S_ + c * 4);
    }
    {
        const float* w2src = isA ? mean_w : logstd_w;
        #pragma unroll
        for (int k = 0; k < 8; k++) {          // 2048 chunks per sub
            int c   = u + k * 256;
            int row = c >> 5;
            int col = c & 31;
            cpa16(WB + row * W2S + col * 4,
                  w2src + ((ull)e * M_ + row) * S_ + col * 4);
        }
    }
    cp_commit();
    cp_wait0();
    __syncthreads();

    // ---- phase 2: 1 row/thread (mg), 4 batches/thread (b0..b0+3) ----
    {
        const int mg = u & 63;              // row, per-lane distinct (banks 4mg)
        const int wq = u >> 6;              // 0..3 -> batch quad (const per warp)
        const int b0 = wq * 4;

        const float* w0 = WB + mg * W2S;
        const float* bsrc = isA ? mean_b : logstd_b;
        const float bias = bsrc[(ull)e * M_ + mg];

        ull acc[4];
        #pragma unroll
        for (int i = 0; i < 4; i++) acc[i] = 0ull;

        #pragma unroll 4
        for (int c = 0; c < 16; c++) {      // 8 s per chunk
            const int s0 = c * 8;
            ulonglong2 wa = *reinterpret_cast<const ulonglong2*>(w0 + s0);
            ulonglong2 wb = *reinterpret_cast<const ulonglong2*>(w0 + s0 + 4);
            #pragma unroll
            for (int i = 0; i < 4; i++) {
                const float* xr = xs + (b0 + i) * S_ + s0;   // warp-broadcast
                ulonglong2 xa = *reinterpret_cast<const ulonglong2*>(xr);
                ulonglong2 xb = *reinterpret_cast<const ulonglong2*>(xr + 4);
                acc[i] = fma2(xa.x, wa.x, acc[i]);
                acc[i] = fma2(xa.y, wa.y, acc[i]);
                acc[i] = fma2(xb.x, wb.x, acc[i]);
                acc[i] = fma2(xb.y, wb.y, acc[i]);
            }
        }

        const ull cellb = (ull)(s_idx * R_ + t_idx) * M_ + mg;
        #pragma unroll
        for (int i = 0; i < 4; i++) {
            const int b = b0 + i;
            float lo, hi;
            unpk(acc[i], lo, hi);
            float v = lo + hi + bias;
            ull a = (ull)b * (R_ * R_ * M_) + cellb;
            if (isA) {
                smean[b * SMS + mg] = v;
                out[OFF_MEAN + a] = v;
                out[OFF_MSG  + a] = v;          // msg == mean
            } else {
                out[OFF_LOG + a] = v;
            }
        }
    }

    // ---- sub barriers: free own weight buffer; publish smean (A -> B) ----
    if (isA) { bar_sync(1, 256); bar_arrive(3, 512); }
    else     { bar_sync(2, 256); }

    // ---- staging 2: phase-3 weights (per sub) ----
    {
        const float* w3src = isA ? add_w : gain_w;
        #pragma unroll
        for (int k = 0; k < 8; k++) {          // 2048 chunks per sub
            int c   = u + k * 256;
            int row = c >> 4;
            int col = c & 15;
            cpa16(WB + row * W3S + col * 4,
                  w3src + ((ull)e * L_ + row) * M_ + col * 4);
        }
    }
    cp_commit();
    cp_wait0();
    if (isA) { bar_sync(1, 256); }
    else     { bar_sync(2, 256); bar_sync(3, 512); }  // wait smean from SubA

    // ---- phase 3: 2 rows/thread (lp, lp+64), 4 batches/thread (bq3+4i) ----
    {
        const int lp  = u >> 2;             // 0..63 (quad-shared -> bcast weights)
        const int bq3 = u & 3;              // 0..3

        const float* wr0 = WB + lp * W3S;
        const float* wr1 = WB + (lp + 64) * W3S;

        ull acc[2][4];
        #pragma unroll
        for (int r = 0; r < 2; r++)
            #pragma unroll
            for (int i = 0; i < 4; i++) acc[r][i] = 0ull;

        #pragma unroll 2
        for (int c = 0; c < 8; c++) {       // 8 m per chunk
            const int m0 = c * 8;
            ulonglong2 wa0 = *reinterpret_cast<const ulonglong2*>(wr0 + m0);
            ulonglong2 wb0 = *reinterpret_cast<const ulonglong2*>(wr0 + m0 + 4);
            ulonglong2 wa1 = *reinterpret_cast<const ulonglong2*>(wr1 + m0);
            ulonglong2 wb1 = *reinterpret_cast<const ulonglong2*>(wr1 + m0 + 4);
            #pragma unroll
            for (int i = 0; i < 4; i++) {
                const int b = bq3 + 4 * i;
                const float* mr = smean + b * SMS + m0;
                ulonglong2 xa = *reinterpret_cast<const ulonglong2*>(mr);
                ulonglong2 xb = *reinterpret_cast<const ulonglong2*>(mr + 4);
                acc[0][i] = fma2(xa.x, wa0.x, acc[0][i]);
                acc[0][i] = fma2(xa.y, wa0.y, acc[0][i]);
                acc[0][i] = fma2(xb.x, wb0.x, acc[0][i]);
                acc[0][i] = fma2(xb.y, wb0.y, acc[0][i]);
                acc[1][i] = fma2(xa.x, wa1.x, acc[1][i]);
                acc[1][i] = fma2(xa.y, wa1.y, acc[1][i]);
                acc[1][i] = fma2(xb.x, wb1.x, acc[1][i]);
                acc[1][i] = fma2(xb.y, wb1.y, acc[1][i]);
            }
        }

        float* sres = isA ? sadd : sgain;
        #pragma unroll
        for (int r = 0; r < 2; r++) {
            const int l = lp + 64 * r;
            #pragma unroll
            for (int i = 0; i < 4; i++) {
                const int b = bq3 + 4 * i;
                float lo, hi;
                unpk(acc[r][i], lo, hi);
                sres[b * SAS + l] = lo + hi;
            }
        }
    }
    if (isA) bar_sync(1, 256);
    else     bar_sync(2, 256);

    // ---- phase 4: vectorized scatter-add (each sub reduces its own array) ----
    {
        float* sres = isA ? sadd : sgain;
        const ull offI = isA ? OFF_INC_ADD : OFF_INC_GAIN;
        #pragma unroll
        for (int k = 0; k < 2; k++) {
            int i = u + 256 * k;
            int b = i >> 5;
            int q = i & 31;
            float4 v = *reinterpret_cast<const float4*>(sres + b * SAS + q * 4);
            float* dst = out + offI + (ull)(b * R_ + t_idx) * L_ + q * 4;
            red_add_v4(dst, v);
        }
    }
}

extern "C" void kernel_launch(void* const* d_in, const int* in_sizes, int n_in,
                              void* d_out, int out_size) {
    const float* source   = (const float*)d_in[0];
    const float* mean_w   = (const float*)d_in[1];
    const float* mean_b   = (const float*)d_in[2];
    const float* logstd_w = (const float*)d_in[3];
    const float* logstd_b = (const float*)d_in[4];
    const float* add_w    = (const float*)d_in[5];
    const float* gain_w   = (const float*)d_in[6];
    float* out = (float*)d_out;

    cudaFuncSetAttribute(edge_kernel, cudaFuncAttributeMaxDynamicSharedMemorySize,
                         SMEM_FLOATS * 4);

    init_kernel<<<256, 256>>>(out);
    edge_kernel<<<E_, 512, SMEM_FLOATS * 4>>>(source, mean_w, mean_b,
                                              logstd_w, logstd_b,
                                              add_w, gain_w, out);
}

// round 17
// speedup vs baseline: 1.1861x; 1.1861x over previous
#include <cuda_runtime.h>
#include <cuda_bf16.h>

// Problem constants
#define B_  16
#define R_  64
#define S_  128
#define M_  64
#define L_  128
#define E_  4032            // R*R - R

// Output layout (float elements), 5 concatenated outputs:
#define OFF_INC_ADD  0ull
#define OFF_INC_GAIN 131072ull
#define OFF_MEAN     262144ull
#define OFF_LOG      4456448ull
#define OFF_MSG      8650752ull

// Shared layout (floats), total 24768 floats = 99072 B dynamic smem  [= R14]
#define XS_OFF    0            // xs[b][s] stride 128: 2048
#define PA_OFF    2048         // SubA weights: w2 64*132=8448 / w3 128*68=8704
#define QB_OFF    10752        // SubB weights
#define SMEAN_OFF 19456        // smean[b][m] stride 68: 1088 -> ends 20544
#define SADD_OFF  20544        // sadd[b][l]  stride 132: 2112 -> ends 22656
#define SGAIN_OFF 22656        // sgain[b][l] stride 132: 2112 -> ends 24768
#define SMEM_FLOATS 24768
#define W2S 132                // phase-2 weight row stride (128+4)
#define W3S 68                 // phase-3 weight row stride (64+4)
#define SMS 68                 // smean row stride
#define SAS 132                // sadd/sgain row stride

typedef unsigned long long ull;

// ---------------- packed f32x2 helpers ----------------
__device__ __forceinline__ ull fma2(ull a, ull b, ull c) {
    ull d;
    asm("fma.rn.f32x2 %0, %1, %2, %3;" : "=l"(d) : "l"(a), "l"(b), "l"(c));
    return d;
}
__device__ __forceinline__ void unpk(ull v, float& lo, float& hi) {
    asm("mov.b64 {%0, %1}, %2;" : "=f"(lo), "=f"(hi) : "l"(v));
}
__device__ __forceinline__ void red_add_v4(float* p, float4 v) {
    asm volatile("red.global.add.v4.f32 [%0], {%1, %2, %3, %4};"
                 :: "l"(p), "f"(v.x), "f"(v.y), "f"(v.z), "f"(v.w) : "memory");
}
__device__ __forceinline__ void cpa16(float* dst_smem, const float* src) {
    unsigned sa = (unsigned)__cvta_generic_to_shared(dst_smem);
    asm volatile("cp.async.cg.shared.global [%0], [%1], 16;" :: "r"(sa), "l"(src));
}
__device__ __forceinline__ void cp_commit() { asm volatile("cp.async.commit_group;"); }
__device__ __forceinline__ void cp_wait1()  { asm volatile("cp.async.wait_group 1;" ::: "memory"); }
__device__ __forceinline__ void cp_wait0()  { asm volatile("cp.async.wait_group 0;" ::: "memory"); }
__device__ __forceinline__ void bar_sync(int id, int cnt) {
    asm volatile("bar.sync %0, %1;" :: "r"(id), "r"(cnt) : "memory");
}
__device__ __forceinline__ void bar_arrive(int id, int cnt) {
    asm volatile("bar.arrive %0, %1;" :: "r"(id), "r"(cnt) : "memory");
}

// ---------------- init: zero inc regions + scat diagonals (vectorized) ----
__global__ void init_kernel(float* __restrict__ out) {
    int idx = blockIdx.x * blockDim.x + threadIdx.x;   // grid covers 65536
    if (idx < 65536)
        reinterpret_cast<float4*>(out)[idx] = make_float4(0.f, 0.f, 0.f, 0.f);
    if (idx < 49152) {
        int o    = idx >> 14;              // 0..2
        int rest = idx & 16383;
        int b    = rest >> 10;             // 0..15
        int r    = (rest >> 4) & 63;       // 0..63
        int q    = rest & 15;              // 0..15
        ull base = (o == 0) ? OFF_MEAN : ((o == 1) ? OFF_LOG : OFF_MSG);
        ull a = base + (((ull)(b * R_ + r) * R_ + r) * M_) + q * 4;
        *reinterpret_cast<float4*>(out + a) = make_float4(0.f, 0.f, 0.f, 0.f);
    }
}

// ---------------- main: one block per edge, two 128-thread sub-pipelines ----
__global__ __launch_bounds__(256, 2) void edge_kernel(
    const float* __restrict__ source,
    const float* __restrict__ mean_w,
    const float* __restrict__ mean_b,
    const float* __restrict__ logstd_w,
    const float* __restrict__ logstd_b,
    const float* __restrict__ add_w,
    const float* __restrict__ gain_w,
    float* __restrict__ out)
{
    extern __shared__ float sm[];
    float* xs    = sm + XS_OFF;      // [b][s] stride 128 (warp-broadcast reads)
    float* smean = sm + SMEAN_OFF;   // [b][m] stride 68
    float* sadd  = sm + SADD_OFF;    // [b][l] stride 132
    float* sgain = sm + SGAIN_OFF;

    const int e = blockIdx.x;
    const int s_idx = e / (R_ - 1);
    const int rem   = e % (R_ - 1);
    const int t_idx = rem + (rem >= s_idx ? 1 : 0);
    const int tid = threadIdx.x;
    const bool isA = (tid < 128);
    const int  u   = tid & 127;
    const int  barid = isA ? 1 : 2;
    float* WB = sm + (isA ? PA_OFF : QB_OFF);

    const float* w2src = isA ? mean_w : logstd_w;
    const float* w3src = isA ? add_w  : gain_w;

    // ---- staging 1, group g1: xs (all threads) + w2 cols 0-63 (per sub) ----
    #pragma unroll
    for (int k = 0; k < 2; k++) {
        int i = tid + k * 256;
        int b = i >> 5, c = i & 31;
        cpa16(xs + 4 * i,
              source + (ull)b * (R_ * S_) + (ull)s_idx * S_ + c * 4);
    }
    #pragma unroll
    for (int k = 0; k < 8; k++) {          // 1024 chunks: 64 rows x cols 0-15
        int c   = u + k * 128;
        int row = c >> 4;
        int col = c & 15;
        cpa16(WB + row * W2S + col * 4,
              w2src + ((ull)e * M_ + row) * S_ + col * 4);
    }
    cp_commit();                            // g1 = xs + w2 s[0:64)

    // ---- staging 1, group g2: w2 cols 64-127 ----
    #pragma unroll
    for (int k = 0; k < 8; k++) {
        int c   = u + k * 128;
        int row = c >> 4;
        int col = c & 15;
        cpa16(WB + row * W2S + 64 + col * 4,
              w2src + ((ull)e * M_ + row) * S_ + 64 + col * 4);
    }
    cp_commit();                            // g2 = w2 s[64:128)

    // ---- phase-2 setup + bias prefetch (overlaps staging latency) ----
    const int warpu = u >> 5;               // 0..3 -> batch quad
    const int mg    = u & 31;
    const int b0    = warpu * 4;
    const float* bsrc = isA ? mean_b : logstd_b;
    const float bias0 = bsrc[(ull)e * M_ + mg];
    const float bias1 = bsrc[(ull)e * M_ + mg + 32];

    const float* w0 = WB + mg * W2S;
    const float* w1 = WB + (mg + 32) * W2S;

    ull acc[2][4];
    #pragma unroll
    for (int r = 0; r < 2; r++)
        #pragma unroll
        for (int b = 0; b < 4; b++) acc[r][b] = 0ull;

    cp_wait1();                             // g1 done (xs + w2 first half)
    __syncthreads();

    // ---- phase 2a: chunks 0-7 (s < 64)  [mapping = R14] ----
    #pragma unroll
    for (int c = 0; c < 8; c++) {
        const int s0 = c * 8;
        ulonglong2 wa0 = *reinterpret_cast<const ulonglong2*>(w0 + s0);
        ulonglong2 wb0 = *reinterpret_cast<const ulonglong2*>(w0 + s0 + 4);
        ulonglong2 wa1 = *reinterpret_cast<const ulonglong2*>(w1 + s0);
        ulonglong2 wb1 = *reinterpret_cast<const ulonglong2*>(w1 + s0 + 4);
        #pragma unroll
        for (int b = 0; b < 4; b++) {
            const float* xr = xs + (b0 + b) * S_ + s0;   // warp-broadcast
            ulonglong2 xa = *reinterpret_cast<const ulonglong2*>(xr);
            ulonglong2 xb = *reinterpret_cast<const ulonglong2*>(xr + 4);
            acc[0][b] = fma2(xa.x, wa0.x, acc[0][b]);
            acc[0][b] = fma2(xa.y, wa0.y, acc[0][b]);
            acc[0][b] = fma2(xb.x, wb0.x, acc[0][b]);
            acc[0][b] = fma2(xb.y, wb0.y, acc[0][b]);
            acc[1][b] = fma2(xa.x, wa1.x, acc[1][b]);
            acc[1][b] = fma2(xa.y, wa1.y, acc[1][b]);
            acc[1][b] = fma2(xb.x, wb1.x, acc[1][b]);
            acc[1][b] = fma2(xb.y, wb1.y, acc[1][b]);
        }
    }

    cp_wait0();                             // g2 done (w2 second half)
    bar_sync(barid, 128);                   // all sub threads' g2 visible

    // ---- phase 2b: chunks 8-15 (s >= 64) ----
    #pragma unroll
    for (int c = 8; c < 16; c++) {
        const int s0 = c * 8;
        ulonglong2 wa0 = *reinterpret_cast<const ulonglong2*>(w0 + s0);
        ulonglong2 wb0 = *reinterpret_cast<const ulonglong2*>(w0 + s0 + 4);
        ulonglong2 wa1 = *reinterpret_cast<const ulonglong2*>(w1 + s0);
        ulonglong2 wb1 = *reinterpret_cast<const ulonglong2*>(w1 + s0 + 4);
        #pragma unroll
        for (int b = 0; b < 4; b++) {
            const float* xr = xs + (b0 + b) * S_ + s0;
            ulonglong2 xa = *reinterpret_cast<const ulonglong2*>(xr);
            ulonglong2 xb = *reinterpret_cast<const ulonglong2*>(xr + 4);
            acc[0][b] = fma2(xa.x, wa0.x, acc[0][b]);
            acc[0][b] = fma2(xa.y, wa0.y, acc[0][b]);
            acc[0][b] = fma2(xb.x, wb0.x, acc[0][b]);
            acc[0][b] = fma2(xb.y, wb0.y, acc[0][b]);
            acc[1][b] = fma2(xa.x, wa1.x, acc[1][b]);
            acc[1][b] = fma2(xa.y, wa1.y, acc[1][b]);
            acc[1][b] = fma2(xb.x, wb1.x, acc[1][b]);
            acc[1][b] = fma2(xb.y, wb1.y, acc[1][b]);
        }
    }

    // ---- phase-2 epilogue  [= R14] ----
    {
        const ull cellb = (ull)(s_idx * R_ + t_idx) * M_;
        #pragma unroll
        for (int r = 0; r < 2; r++) {
            const int m = mg + 32 * r;
            const float bias = r ? bias1 : bias0;
            #pragma unroll
            for (int b = 0; b < 4; b++) {
                float lo, hi;
                unpk(acc[r][b], lo, hi);
                float v = lo + hi + bias;
                ull a = (ull)(b0 + b) * (R_ * R_ * M_) + cellb + m;
                if (isA) {
                    smean[(b0 + b) * SMS + m] = v;
                    out[OFF_MEAN + a] = v;
                    out[OFF_MSG  + a] = v;          // msg == mean
                } else {
                    out[OFF_LOG + a] = v;
                }
            }
        }
    }

    // ---- sub barriers: free own weight buffer; publish smean (A -> B) ----
    if (isA) { bar_sync(1, 128); bar_arrive(3, 256); }
    else     { bar_sync(2, 128); }

    // ---- staging 2, group g3: w3 rows 0-63 ----
    #pragma unroll
    for (int k = 0; k < 8; k++) {
        int c   = u + k * 128;
        int row = c >> 4;                   // 0..63
        int col = c & 15;
        cpa16(WB + row * W3S + col * 4,
              w3src + ((ull)e * L_ + row) * M_ + col * 4);
    }
    cp_commit();                            // g3 = w3 rows [0:64)

    // ---- staging 2, group g4: w3 rows 64-127 ----
    #pragma unroll
    for (int k = 0; k < 8; k++) {
        int c   = u + k * 128;
        int row = c >> 4;
        int col = c & 15;
        cpa16(WB + (64 + row) * W3S + col * 4,
              w3src + ((ull)e * L_ + 64 + row) * M_ + col * 4);
    }
    cp_commit();                            // g4 = w3 rows [64:128)

    cp_wait1();                             // g3 done
    if (isA) { bar_sync(1, 128); }
    else     { bar_sync(2, 128); bar_sync(3, 256); }  // + smean from SubA

    const int lp  = u >> 2;                 // 0..31 (quad-shared -> bcast weights)
    const int bq3 = u & 3;                  // 0..3
    float* sres = isA ? sadd : sgain;

    // ---- phase 3a: rows lp, lp+32  [mapping = R14 rows r=0,1] ----
    {
        ull acc3[2][4];
        #pragma unroll
        for (int r = 0; r < 2; r++)
            #pragma unroll
            for (int i = 0; i < 4; i++) acc3[r][i] = 0ull;

        #pragma unroll
        for (int c = 0; c < 8; c++) {
            const int m0 = c * 8;
            ulonglong2 wa[2], wb[2];
            #pragma unroll
            for (int r = 0; r < 2; r++) {
                const float* wr = WB + (lp + 32 * r) * W3S + m0;
                wa[r] = *reinterpret_cast<const ulonglong2*>(wr);
                wb[r] = *reinterpret_cast<const ulonglong2*>(wr + 4);
            }
            #pragma unroll
            for (int i = 0; i < 4; i++) {
                const int b = bq3 + 4 * i;
                const float* mr = smean + b * SMS + m0;
                ulonglong2 xa = *reinterpret_cast<const ulonglong2*>(mr);
                ulonglong2 xb = *reinterpret_cast<const ulonglong2*>(mr + 4);
                #pragma unroll
                for (int r = 0; r < 2; r++) {
                    acc3[r][i] = fma2(xa.x, wa[r].x, acc3[r][i]);
                    acc3[r][i] = fma2(xa.y, wa[r].y, acc3[r][i]);
                    acc3[r][i] = fma2(xb.x, wb[r].x, acc3[r][i]);
                    acc3[r][i] = fma2(xb.y, wb[r].y, acc3[r][i]);
                }
            }
        }
        #pragma unroll
        for (int r = 0; r < 2; r++) {
            const int l = lp + 32 * r;
            #pragma unroll
            for (int i = 0; i < 4; i++) {
                const int b = bq3 + 4 * i;
                float lo, hi;
                unpk(acc3[r][i], lo, hi);
                sres[b * SAS + l] = lo + hi;
            }
        }
    }

    cp_wait0();                             // g4 done
    bar_sync(barid, 128);                   // all sub threads' g4 visible

    // ---- phase 3b: rows 64+lp, 96+lp ----
    {
        ull acc3[2][4];
        #pragma unroll
        for (int r = 0; r < 2; r++)
            #pragma unroll
            for (int i = 0; i < 4; i++) acc3[r][i] = 0ull;

        #pragma unroll
        for (int c = 0; c < 8; c++) {
            const int m0 = c * 8;
            ulonglong2 wa[2], wb[2];
            #pragma unroll
            for (int r = 0; r < 2; r++) {
                const float* wr = WB + (64 + lp + 32 * r) * W3S + m0;
                wa[r] = *reinterpret_cast<const ulonglong2*>(wr);
                wb[r] = *reinterpret_cast<const ulonglong2*>(wr + 4);
            }
            #pragma unroll
            for (int i = 0; i < 4; i++) {
                const int b = bq3 + 4 * i;
                const float* mr = smean + b * SMS + m0;
                ulonglong2 xa = *reinterpret_cast<const ulonglong2*>(mr);
                ulonglong2 xb = *reinterpret_cast<const ulonglong2*>(mr + 4);
                #pragma unroll
                for (int r = 0; r < 2; r++) {
                    acc3[r][i] = fma2(xa.x, wa[r].x, acc3[r][i]);
                    acc3[r][i] = fma2(xa.y, wa[r].y, acc3[r][i]);
                    acc3[r][i] = fma2(xb.x, wb[r].x, acc3[r][i]);
                    acc3[r][i] = fma2(xb.y, wb[r].y, acc3[r][i]);
                }
            }
        }
        #pragma unroll
        for (int r = 0; r < 2; r++) {
            const int l = 64 + lp + 32 * r;
            #pragma unroll
            for (int i = 0; i < 4; i++) {
                const int b = bq3 + 4 * i;
                float lo, hi;
                unpk(acc3[r][i], lo, hi);
                sres[b * SAS + l] = lo + hi;
            }
        }
    }
    if (isA) bar_sync(1, 128);
    else     bar_sync(2, 128);

    // ---- phase 4: vectorized scatter-add (each sub reduces its own array) ----
    {
        const ull offI = isA ? OFF_INC_ADD : OFF_INC_GAIN;
        #pragma unroll
        for (int k = 0; k < 4; k++) {
            int i = u + 128 * k;
            int b = i >> 5;
            int q = i & 31;
            float4 v = *reinterpret_cast<const float4*>(sres + b * SAS + q * 4);
            float* dst = out + offI + (ull)(b * R_ + t_idx) * L_ + q * 4;
            red_add_v4(dst, v);
        }
    }
}

extern "C" void kernel_launch(void* const* d_in, const int* in_sizes, int n_in,
                              void* d_out, int out_size) {
    const float* source   = (const float*)d_in[0];
    const float* mean_w   = (const float*)d_in[1];
    const float* mean_b   = (const float*)d_in[2];
    const float* logstd_w = (const float*)d_in[3];
    const float* logstd_b = (const float*)d_in[4];
    const float* add_w    = (const float*)d_in[5];
    const float* gain_w   = (const float*)d_in[6];
    float* out = (float*)d_out;

    cudaFuncSetAttribute(edge_kernel, cudaFuncAttributeMaxDynamicSharedMemorySize,
                         SMEM_FLOATS * 4);

    init_kernel<<<256, 256>>>(out);
    edge_kernel<<<E_, 256, SMEM_FLOATS * 4>>>(source, mean_w, mean_b,
                                              logstd_w, logstd_b,
                                              add_w, gain_w, out);
}